// round 13
// baseline (speedup 1.0000x reference)
#include <cuda_runtime.h>
#include <cuda_fp16.h>
#include <cstdint>
#include <math.h>

// Problem dims
#define Hd 2048
#define Ed 16
#define Td 2048
#define Id 1408
#define ISd 2816

// ---------------- scratch (static device globals; no allocs) ----------------
__device__ __half g_xh[2048 * 2048];           // x in fp16 (written by router)
__device__ __half g_wg_h[16 * 2048 * 1408];    // routed gate weights fp16
__device__ __half g_wu_h[16 * 2048 * 1408];    // routed up weights fp16
__device__ __half g_wd_h[16 * 1408 * 2048];    // routed down weights fp16
__device__ __half g_wsg_h[2048 * 2816];        // shared gate fp16
__device__ __half g_wsu_h[2048 * 2816];        // shared up fp16
__device__ __half g_wsd_h[2816 * 2048];        // shared down fp16
__device__ __half g_act[4096 * 1408];          // compact routed activations fp16
__device__ __half g_sact[2048 * 2816];         // shared-expert activations fp16
__device__ int   g_slot_token[4096];
__device__ float g_slot_w[4096];
__device__ int   g_topk_idx[2048 * 2];
__device__ float g_topk_w[2048 * 2];
__device__ int   g_counts[16];
__device__ int   g_offs[16];

// ---------------- helpers ----------------
__device__ __forceinline__ void mma16(float* c, const uint32_t* a, uint32_t b0, uint32_t b1) {
    asm volatile(
        "mma.sync.aligned.m16n8k16.row.col.f32.f16.f16.f32 "
        "{%0,%1,%2,%3}, {%4,%5,%6,%7}, {%8,%9}, {%0,%1,%2,%3};\n"
        : "+f"(c[0]), "+f"(c[1]), "+f"(c[2]), "+f"(c[3])
        : "r"(a[0]), "r"(a[1]), "r"(a[2]), "r"(a[3]), "r"(b0), "r"(b1));
}

__device__ __forceinline__ void cp16h(__half* s, const __half* g, bool pred) {
    uint32_t sa = (uint32_t)__cvta_generic_to_shared(s);
    int sz = pred ? 16 : 0;
    asm volatile("cp.async.cg.shared.global [%0], [%1], 16, %2;\n"
                 :: "r"(sa), "l"(g), "r"(sz));
}
#define CP_COMMIT() asm volatile("cp.async.commit_group;\n")

__device__ __forceinline__ uint32_t s2u(const void* p) {
    return (uint32_t)__cvta_generic_to_shared(p);
}

__device__ __forceinline__ void ldsm4(uint32_t* r, uint32_t a) {
    asm volatile("ldmatrix.sync.aligned.m8n8.x4.shared.b16 {%0,%1,%2,%3}, [%4];"
                 : "=r"(r[0]), "=r"(r[1]), "=r"(r[2]), "=r"(r[3]) : "r"(a));
}
__device__ __forceinline__ void ldsm4t(uint32_t* r, uint32_t a) {
    asm volatile("ldmatrix.sync.aligned.m8n8.x4.trans.shared.b16 {%0,%1,%2,%3}, [%4];"
                 : "=r"(r[0]), "=r"(r[1]), "=r"(r[2]), "=r"(r[3]) : "r"(a));
}

__device__ __forceinline__ void cvt_store(uint2* dst, const float4* src, uint32_t off) {
    float4 v = src[off];
    __half2 h0 = __floats2half2_rn(v.x, v.y);
    __half2 h1 = __floats2half2_rn(v.z, v.w);
    dst[off] = make_uint2(*(uint32_t*)&h0, *(uint32_t*)&h1);
}

// ---------------- phase-1 conversion (weights needed by gate/up) ------------
// Segments in float4 units: wg, wu, wsg, wsu.
#define S_WGE  11534336u                // 16*2048*1408/4
#define S_WS   1441792u                 // 2048*2816/4
#define P1_0 (S_WGE)
#define P1_1 (P1_0 + S_WGE)
#define P1_2 (P1_1 + S_WS)
#define P1_3 (P1_2 + S_WS)             // total = 25952256

__global__ void __launch_bounds__(256) cvt1_kernel(
    const float4* __restrict__ wg,  const float4* __restrict__ wu,
    const float4* __restrict__ wsg, const float4* __restrict__ wsu) {
    for (uint32_t i = blockIdx.x * blockDim.x + threadIdx.x; i < P1_3;
         i += gridDim.x * blockDim.x) {
        if (i < P1_0)      cvt_store((uint2*)g_wg_h,  wg,  i);
        else if (i < P1_1) cvt_store((uint2*)g_wu_h,  wu,  i - P1_0);
        else if (i < P1_2) cvt_store((uint2*)g_wsg_h, wsg, i - P1_1);
        else               cvt_store((uint2*)g_wsu_h, wsu, i - P1_2);
    }
}

// ---------------- dispatch: histogram + scan + slot build (1 block) ---------
__global__ void __launch_bounds__(1024) dispatch_kernel() {
    __shared__ int hist[16];
    __shared__ int soffs[16];
    __shared__ int scur[16];
    int tid = threadIdx.x;
    if (tid < 16) { hist[tid] = 0; scur[tid] = 0; }
    __syncthreads();
    for (int i = tid; i < Td * 2; i += 1024)
        atomicAdd(&hist[g_topk_idx[i]], 1);
    __syncthreads();
    if (tid == 0) {
        int off = 0;
        #pragma unroll
        for (int e = 0; e < 16; e++) {
            soffs[e] = off; g_offs[e] = off; g_counts[e] = hist[e]; off += hist[e];
        }
    }
    __syncthreads();
    for (int t = tid; t < Td; t += 1024) {
        #pragma unroll
        for (int k = 0; k < 2; k++) {
            int e = g_topk_idx[2 * t + k];
            int p = atomicAdd(&scur[e], 1);
            int s = soffs[e] + p;
            g_slot_token[s] = t;
            g_slot_w[s] = g_topk_w[2 * t + k];
        }
    }
}

// One warp per token: logits -> softmax -> top-2.
// Also emits the fp16 copy of x (row already resident in registers).
// No global histogram (dispatch rebuilds it from g_topk_idx).
__global__ void __launch_bounds__(128) router_kernel(const float* __restrict__ x,
                                                     const float* __restrict__ gw) {
    int lane = threadIdx.x & 31;
    int t = blockIdx.x * 4 + (threadIdx.x >> 5);
    if (t >= Td) return;
    float xr[64];
    const float* xp = x + (size_t)t * Hd;
    #pragma unroll
    for (int j = 0; j < 64; j++) xr[j] = xp[lane + 32 * j];
    __half* xh = g_xh + (size_t)t * Hd;
    #pragma unroll
    for (int j = 0; j < 64; j++) xh[lane + 32 * j] = __float2half_rn(xr[j]);
    float logit[16];
    #pragma unroll
    for (int e = 0; e < 16; e++) {
        const float* g = gw + e * Hd;
        float s = 0.f;
        #pragma unroll
        for (int j = 0; j < 64; j++) s = fmaf(xr[j], g[lane + 32 * j], s);
        #pragma unroll
        for (int o = 16; o > 0; o >>= 1) s += __shfl_xor_sync(0xffffffffu, s, o);
        logit[e] = s;
    }
    if (lane == 0) {
        float mx = logit[0];
        #pragma unroll
        for (int e = 1; e < 16; e++) mx = fmaxf(mx, logit[e]);
        float p[16]; float den = 0.f;
        #pragma unroll
        for (int e = 0; e < 16; e++) { p[e] = expf(logit[e] - mx); den += p[e]; }
        int i1 = 0; float v1 = p[0];
        #pragma unroll
        for (int e = 1; e < 16; e++) if (p[e] > v1) { v1 = p[e]; i1 = e; }
        int i2 = -1; float v2 = -1.f;
        #pragma unroll
        for (int e = 0; e < 16; e++) if (e != i1 && p[e] > v2) { v2 = p[e]; i2 = e; }
        float inv = 1.f / den;
        g_topk_idx[2 * t]     = i1;
        g_topk_idx[2 * t + 1] = i2;
        g_topk_w[2 * t]       = v1 * inv;
        g_topk_w[2 * t + 1]   = v2 * inv;
    }
}

// ---------------- gate+up GEMM + overlapped phase-2 conversion --------------
// GEMM tile: 128(M) x 64(N per matrix) x 64(K). 256 threads, warps 4(M)x2(N).
// Stage (halves): A[128][72] (9216), Bg[64][72] (4608), Bu[64][72] (4608).
// 3 stages = 110592 B (2 CTAs/SM). Row stride 144 B -> conflict-free LDSM.
//
// Heterogeneous grid: 3520 GEMM blocks + 4096 cvt blocks, bid-interleaved so
// SMs co-host one tensor-bound GEMM CTA and one DRAM-bound cvt CTA.
// (Register-budget note: both paths here are fine — the cvt path inherits the
// GEMM kernel's ~98-reg budget but is DRAM-bound with 2 CTAs/SM resident,
// measured to still reach full overlap in R8. Do NOT merge the 100+-reg
// router into the 30-reg cvt1 kernel — that coupling cost 100 µs in R10.)
#define GU_GEMM_BLOCKS 3520
#define GU_SHARED_BLOCKS 704
#define CVT2_BLOCKS 4096
#define GU_TOTAL_BLOCKS (GU_GEMM_BLOCKS + CVT2_BLOCKS)   // 7616
#define GU_IL (2 * GU_GEMM_BLOCKS)                       // 7040 interleave zone

// phase-2 segments in float4 units: wd, wsd, out-zero
#define P2_0 (S_WGE)                    // wd     = 11534336
#define P2_1 (P2_0 + S_WS)              // +wsd   = 12976128
#define P2_2 (P2_1 + 1048576u)          // +out   = 14024704

__global__ void __launch_bounds__(256) gateup_all_kernel(
    const float4* __restrict__ wd, const float4* __restrict__ wsd,
    float4* __restrict__ out) {
    extern __shared__ __half sm[];
    __shared__ int tok_s[128];
    const int tid = threadIdx.x;
    const int bid = blockIdx.x;

    // ---- decode heterogeneous grid ----
    int gemm_id, cvt_id;
    if (bid < GU_IL) {
        if (bid & 1) { cvt_id = bid >> 1; gemm_id = -1; }
        else         { gemm_id = bid >> 1; cvt_id = -1; }
    } else {
        cvt_id = GU_GEMM_BLOCKS + (bid - GU_IL); gemm_id = -1;
    }

    if (gemm_id < 0) {
        // ---- phase-2 conversion path (no smem, no syncs) ----
        for (uint32_t i = cvt_id * 256 + tid; i < P2_2; i += CVT2_BLOCKS * 256) {
            if (i < P2_0)      cvt_store((uint2*)g_wd_h,  wd,  i);
            else if (i < P2_1) cvt_store((uint2*)g_wsd_h, wsd, i - P2_0);
            else               out[i - P2_1] = make_float4(0.f, 0.f, 0.f, 0.f);
        }
        return;
    }

    // ---- GEMM path ----
    const int lane = tid & 31, wid = tid >> 5;
    const int wm = wid & 3, wn = wid >> 2;
    bool routed; int e, n0, r0, N;
    if (gemm_id < GU_SHARED_BLOCKS) {
        routed = false; N = ISd; e = 0;
        n0 = (gemm_id % 44) * 64; r0 = (gemm_id / 44) * 128;
    } else {
        int b = gemm_id - GU_SHARED_BLOCKS;
        routed = true; N = Id;
        n0 = (b % 22) * 64; int t = b / 22;
        r0 = (t & 7) * 128; e = t >> 3;
    }

    int C, base;
    if (routed) { C = g_counts[e]; base = g_offs[e]; }
    else        { C = Td;          base = 0; }
    if (r0 >= C) return;

    const __half* WgE = routed ? g_wg_h + (size_t)e * Hd * N : g_wsg_h;
    const __half* WuE = routed ? g_wu_h + (size_t)e * Hd * N : g_wsu_h;
    __half* ACT = routed ? g_act : g_sact;

    if (tid < 128) {
        int r = r0 + tid;
        tok_s[tid] = (r < C) ? (routed ? g_slot_token[base + r] : r) : -1;
    }
    __syncthreads();

    auto issue = [&](int st, int kt) {
        __half* As = sm + st * 18432;
        __half* Bg = As + 9216;
        __half* Bu = Bg + 4608;
        int k0 = kt * 64;
        #pragma unroll
        for (int i = 0; i < 4; i++) {       // A: 128 rows x 8 chunks
            int idx = tid + i * 256;
            int row = idx >> 3, kc = (idx & 7) * 8;
            int tok = tok_s[row];
            const __half* src = g_xh + (size_t)(tok < 0 ? 0 : tok) * Hd + k0 + kc;
            cp16h(&As[row * 72 + kc], src, tok >= 0);
        }
        #pragma unroll
        for (int i = 0; i < 2; i++) {       // B: 64 rows x 8 chunks each matrix
            int idx = tid + i * 256;
            int row = idx >> 3, nc = (idx & 7) * 8;
            size_t go = (size_t)(k0 + row) * N + n0 + nc;
            cp16h(&Bg[row * 72 + nc], WgE + go, true);
            cp16h(&Bu[row * 72 + nc], WuE + go, true);
        }
        CP_COMMIT();
    };

    float accg[2][4][4] = {};
    float accu[2][4][4] = {};

    auto compute = [&](int st) {
        const __half* As = sm + st * 18432;
        const __half* Bg = As + 9216;
        const __half* Bu = Bg + 4608;
        #pragma unroll
        for (int kk = 0; kk < 4; kk++) {
            uint32_t a[2][4];
            #pragma unroll
            for (int mt = 0; mt < 2; mt++) {
                uint32_t ad = s2u(&As[(wm * 32 + mt * 16 + (lane & 15)) * 72 +
                                      kk * 16 + (lane >> 4) * 8]);
                ldsm4(a[mt], ad);
            }
            #pragma unroll
            for (int np = 0; np < 2; np++) {
                uint32_t bg[4], bu[4];
                int rowk = kk * 16 + (lane & 15);
                int ncol = wn * 32 + np * 16 + (lane >> 4) * 8;
                ldsm4t(bg, s2u(&Bg[rowk * 72 + ncol]));
                ldsm4t(bu, s2u(&Bu[rowk * 72 + ncol]));
                #pragma unroll
                for (int j = 0; j < 2; j++) {
                    int nt = np * 2 + j;
                    #pragma unroll
                    for (int mt = 0; mt < 2; mt++) {
                        mma16(accg[mt][nt], a[mt], bg[2 * j], bg[2 * j + 1]);
                        mma16(accu[mt][nt], a[mt], bu[2 * j], bu[2 * j + 1]);
                    }
                }
            }
        }
    };

    const int NK = Hd / 64;  // 32
    issue(0, 0);
    issue(1, 1);
    for (int kt = 0; kt < NK; kt++) {
        if (kt < NK - 1) asm volatile("cp.async.wait_group 1;\n");
        else             asm volatile("cp.async.wait_group 0;\n");
        __syncthreads();
        if (kt + 2 < NK) issue((kt + 2) % 3, kt + 2);
        compute(kt % 3);
    }

    #pragma unroll
    for (int mt = 0; mt < 2; mt++)
    #pragma unroll
    for (int nt = 0; nt < 4; nt++)
    #pragma unroll
    for (int ih = 0; ih < 2; ih++) {
        int rl = wm * 32 + mt * 16 + (lane >> 2) + ih * 8;
        int r = r0 + rl;
        if (r < C) {
            int col = n0 + wn * 32 + nt * 8 + 2 * (lane & 3);
            float g0 = accg[mt][nt][2 * ih], u0 = accu[mt][nt][2 * ih];
            float g1 = accg[mt][nt][2 * ih + 1], u1 = accu[mt][nt][2 * ih + 1];
            float a0 = g0 / (1.f + __expf(-g0)) * u0;
            float a1 = g1 / (1.f + __expf(-g1)) * u1;
            *(__half2*)&ACT[(size_t)(base + r) * N + col] = __floats2half2_rn(a0, a1);
        }
    }
}

// ---------------- merged down-proj GEMM (shared + routed in one launch) -----
// Tile: 128(M) x 128(N) x 64(K). 256 threads, warps 4(M) x 2(N), warp = 32x64.
// Stage (halves): A[128][72] (9216), B[64][136] (8704). 3 st = 107520 B.
// out is pre-zeroed (by gateup's cvt blocks); EVERY epilogue write is
// atomicAdd (shared rows weight 1.0), so block execution order is irrelevant.
#define DN_SHARED_BLOCKS 256
#define DN_TOTAL_BLOCKS  2304
__global__ void __launch_bounds__(256) down_all_kernel(float* __restrict__ out) {
    extern __shared__ __half sm[];
    __shared__ int tok_s[128];
    __shared__ float w_s[128];
    const int tid = threadIdx.x;
    const int lane = tid & 31, wid = tid >> 5;
    const int wm = wid & 3, wn = wid >> 2;
    const int bid = blockIdx.x;

    bool routed; int e, n0, r0, K;
    if (bid < DN_SHARED_BLOCKS) {
        routed = false; K = ISd; e = 0;
        n0 = (bid & 15) * 128; r0 = (bid >> 4) * 128;
    } else {
        int b = bid - DN_SHARED_BLOCKS;
        routed = true; K = Id;
        n0 = (b & 15) * 128; int t = b >> 4;
        r0 = (t & 7) * 128; e = t >> 3;
    }

    int C, base;
    if (routed) { C = g_counts[e]; base = g_offs[e]; }
    else        { C = Td;          base = 0; }
    if (r0 >= C) return;

    const __half* A   = routed ? g_act : g_sact;
    const __half* WdE = routed ? g_wd_h + (size_t)e * K * Hd : g_wsd_h;

    if (tid < 128) {
        int r = r0 + tid;
        bool v = (r < C);
        tok_s[tid] = v ? (routed ? g_slot_token[base + r] : r) : -1;
        w_s[tid]   = v ? (routed ? g_slot_w[base + r] : 1.0f) : 0.f;
    }
    __syncthreads();

    auto issue = [&](int st, int kt) {
        __half* As = sm + st * 17920;
        __half* Bs = As + 9216;
        int k0 = kt * 64;
        #pragma unroll
        for (int i = 0; i < 4; i++) {       // A: 128 rows x 8 chunks
            int idx = tid + i * 256;
            int row = idx >> 3, kc = (idx & 7) * 8;
            bool pred = (r0 + row) < C;
            const __half* src = A + (size_t)(base + (pred ? (r0 + row) : 0)) * K + k0 + kc;
            cp16h(&As[row * 72 + kc], src, pred);
        }
        #pragma unroll
        for (int i = 0; i < 4; i++) {       // B: 64 rows x 16 chunks
            int idx = tid + i * 256;
            int row = idx >> 4, nc = (idx & 15) * 8;
            cp16h(&Bs[row * 136 + nc], WdE + (size_t)(k0 + row) * Hd + n0 + nc, true);
        }
        CP_COMMIT();
    };

    float acc[2][8][4] = {};

    auto compute = [&](int st) {
        const __half* As = sm + st * 17920;
        const __half* Bs = As + 9216;
        #pragma unroll
        for (int kk = 0; kk < 4; kk++) {
            uint32_t a[2][4];
            #pragma unroll
            for (int mt = 0; mt < 2; mt++) {
                uint32_t ad = s2u(&As[(wm * 32 + mt * 16 + (lane & 15)) * 72 +
                                      kk * 16 + (lane >> 4) * 8]);
                ldsm4(a[mt], ad);
            }
            #pragma unroll
            for (int np = 0; np < 4; np++) {
                uint32_t b[4];
                int rowk = kk * 16 + (lane & 15);
                int ncol = wn * 64 + np * 16 + (lane >> 4) * 8;
                ldsm4t(b, s2u(&Bs[rowk * 136 + ncol]));
                #pragma unroll
                for (int j = 0; j < 2; j++) {
                    int nt = np * 2 + j;
                    #pragma unroll
                    for (int mt = 0; mt < 2; mt++)
                        mma16(acc[mt][nt], a[mt], b[2 * j], b[2 * j + 1]);
                }
            }
        }
    };

    const int NK = K / 64;  // 44 (shared) or 22 (routed)
    issue(0, 0);
    issue(1, 1);
    for (int kt = 0; kt < NK; kt++) {
        if (kt < NK - 1) asm volatile("cp.async.wait_group 1;\n");
        else             asm volatile("cp.async.wait_group 0;\n");
        __syncthreads();
        if (kt + 2 < NK) issue((kt + 2) % 3, kt + 2);
        compute(kt % 3);
    }

    #pragma unroll
    for (int mt = 0; mt < 2; mt++)
    #pragma unroll
    for (int nt = 0; nt < 8; nt++)
    #pragma unroll
    for (int i = 0; i < 4; i++) {
        int rl = wm * 32 + mt * 16 + (lane >> 2) + (i >> 1) * 8;
        int col = n0 + wn * 64 + nt * 8 + 2 * (lane & 3) + (i & 1);
        if (r0 + rl < C) {
            int t = tok_s[rl];
            atomicAdd(out + (size_t)t * Hd + col, w_s[rl] * acc[mt][nt][i]);
        }
    }
}

// ---------------- launcher ----------------
extern "C" void kernel_launch(void* const* d_in, const int* in_sizes, int n_in,
                              void* d_out, int out_size) {
    (void)in_sizes; (void)n_in; (void)out_size;
    const float* x   = (const float*)d_in[0];
    const float* gw  = (const float*)d_in[1];
    const float* wg  = (const float*)d_in[2];
    const float* wu  = (const float*)d_in[3];
    const float* wd  = (const float*)d_in[4];
    const float* wsg = (const float*)d_in[5];
    const float* wsu = (const float*)d_in[6];
    const float* wsd = (const float*)d_in[7];
    float* out = (float*)d_out;

    const int GU_SMEM = 3 * 18432 * 2;   // 110592
    const int DN_SMEM = 3 * 17920 * 2;   // 107520
    cudaFuncSetAttribute(gateup_all_kernel, cudaFuncAttributeMaxDynamicSharedMemorySize, GU_SMEM);
    cudaFuncSetAttribute(down_all_kernel,   cudaFuncAttributeMaxDynamicSharedMemorySize, DN_SMEM);

    // 1) router (own launch, own register budget; also writes g_xh fp16)
    router_kernel<<<512, 128>>>(x, gw);

    // 2) dispatch: histogram + scan + compact slot lists (single block)
    dispatch_kernel<<<1, 1024>>>();

    // 3) phase-1 cvt: wg/wu/wsg/wsu (own 30-reg kernel, full occupancy)
    cvt1_kernel<<<8192, 256>>>((const float4*)wg,  (const float4*)wu,
                               (const float4*)wsg, (const float4*)wsu);

    // 4) gate/up GEMM (3520 blocks) + overlapped phase-2 cvt (4096 blocks:
    //    wd, wsd, out-zero), bid-interleaved
    gateup_all_kernel<<<GU_TOTAL_BLOCKS, 256, GU_SMEM>>>(
        (const float4*)wd, (const float4*)wsd, (float4*)out);

    // 5) merged down: atomicAdd onto the pre-zeroed out
    down_all_kernel<<<DN_TOTAL_BLOCKS, 256, DN_SMEM>>>(out);
}

// round 14
// speedup vs baseline: 1.4265x; 1.4265x over previous
#include <cuda_runtime.h>
#include <cuda_fp16.h>
#include <cstdint>
#include <math.h>

// Problem dims
#define Hd 2048
#define Ed 16
#define Td 2048
#define Id 1408
#define ISd 2816

// ---------------- scratch (static device globals; no allocs) ----------------
__device__ __half g_xh[2048 * 2048];           // x in fp16 (written by router)
__device__ __half g_wg_h[16 * 2048 * 1408];    // routed gate weights fp16
__device__ __half g_wu_h[16 * 2048 * 1408];    // routed up weights fp16
__device__ __half g_wd_h[16 * 1408 * 2048];    // routed down weights fp16
__device__ __half g_wsg_h[2048 * 2816];        // shared gate fp16
__device__ __half g_wsu_h[2048 * 2816];        // shared up fp16
__device__ __half g_wsd_h[2816 * 2048];        // shared down fp16
__device__ __half g_act[4096 * 1408];          // compact routed activations fp16
__device__ __half g_sact[2048 * 2816];         // shared-expert activations fp16
__device__ int   g_slot_token[4096];
__device__ float g_slot_w[4096];
__device__ int   g_topk_idx[2048 * 2];
__device__ float g_topk_w[2048 * 2];
__device__ int   g_counts[16];
__device__ int   g_offs[16];

// ---------------- helpers ----------------
__device__ __forceinline__ void mma16(float* c, const uint32_t* a, uint32_t b0, uint32_t b1) {
    asm volatile(
        "mma.sync.aligned.m16n8k16.row.col.f32.f16.f16.f32 "
        "{%0,%1,%2,%3}, {%4,%5,%6,%7}, {%8,%9}, {%0,%1,%2,%3};\n"
        : "+f"(c[0]), "+f"(c[1]), "+f"(c[2]), "+f"(c[3])
        : "r"(a[0]), "r"(a[1]), "r"(a[2]), "r"(a[3]), "r"(b0), "r"(b1));
}

__device__ __forceinline__ void cp16h(__half* s, const __half* g, bool pred) {
    uint32_t sa = (uint32_t)__cvta_generic_to_shared(s);
    int sz = pred ? 16 : 0;
    asm volatile("cp.async.cg.shared.global [%0], [%1], 16, %2;\n"
                 :: "r"(sa), "l"(g), "r"(sz));
}
#define CP_COMMIT() asm volatile("cp.async.commit_group;\n")

__device__ __forceinline__ uint32_t s2u(const void* p) {
    return (uint32_t)__cvta_generic_to_shared(p);
}

__device__ __forceinline__ void ldsm4(uint32_t* r, uint32_t a) {
    asm volatile("ldmatrix.sync.aligned.m8n8.x4.shared.b16 {%0,%1,%2,%3}, [%4];"
                 : "=r"(r[0]), "=r"(r[1]), "=r"(r[2]), "=r"(r[3]) : "r"(a));
}
__device__ __forceinline__ void ldsm4t(uint32_t* r, uint32_t a) {
    asm volatile("ldmatrix.sync.aligned.m8n8.x4.trans.shared.b16 {%0,%1,%2,%3}, [%4];"
                 : "=r"(r[0]), "=r"(r[1]), "=r"(r[2]), "=r"(r[3]) : "r"(a));
}

__device__ __forceinline__ void cvt_store(uint2* dst, const float4* src, uint32_t off) {
    float4 v = src[off];
    __half2 h0 = __floats2half2_rn(v.x, v.y);
    __half2 h1 = __floats2half2_rn(v.z, v.w);
    dst[off] = make_uint2(*(uint32_t*)&h0, *(uint32_t*)&h1);
}

// ---------------- phase-1 conversion (weights needed by gate/up) ------------
// Segments in float4 units: wg, wu, wsg, wsu.
#define S_WGE  11534336u                // 16*2048*1408/4
#define S_WS   1441792u                 // 2048*2816/4
#define P1_0 (S_WGE)
#define P1_1 (P1_0 + S_WGE)
#define P1_2 (P1_1 + S_WS)
#define P1_3 (P1_2 + S_WS)             // total = 25952256

__global__ void __launch_bounds__(256) cvt1_kernel(
    const float4* __restrict__ wg,  const float4* __restrict__ wu,
    const float4* __restrict__ wsg, const float4* __restrict__ wsu) {
    for (uint32_t i = blockIdx.x * blockDim.x + threadIdx.x; i < P1_3;
         i += gridDim.x * blockDim.x) {
        if (i < P1_0)      cvt_store((uint2*)g_wg_h,  wg,  i);
        else if (i < P1_1) cvt_store((uint2*)g_wu_h,  wu,  i - P1_0);
        else if (i < P1_2) cvt_store((uint2*)g_wsg_h, wsg, i - P1_1);
        else               cvt_store((uint2*)g_wsu_h, wsu, i - P1_2);
    }
}

// ---------------- tiny kernels ----------------
__global__ void zero_kernel() {
    if (threadIdx.x < 16) g_counts[threadIdx.x] = 0;
}

// Single block: prefix scan over counts + compact slot-list build.
__global__ void __launch_bounds__(1024) dispatch_kernel() {
    __shared__ int soffs[16];
    __shared__ int scur[16];
    int tid = threadIdx.x;
    if (tid == 0) {
        int off = 0;
        #pragma unroll
        for (int e = 0; e < 16; e++) {
            soffs[e] = off; g_offs[e] = off; off += g_counts[e];
        }
    }
    if (tid < 16) scur[tid] = 0;
    __syncthreads();
    for (int t = tid; t < Td; t += 1024) {
        #pragma unroll
        for (int k = 0; k < 2; k++) {
            int e = g_topk_idx[2 * t + k];
            int p = atomicAdd(&scur[e], 1);
            int s = soffs[e] + p;
            g_slot_token[s] = t;
            g_slot_w[s] = g_topk_w[2 * t + k];
        }
    }
}

// One warp per token: logits -> softmax -> top-2 -> histogram.
// Also emits the fp16 copy of x (row already resident in registers).
__global__ void __launch_bounds__(128) router_kernel(const float* __restrict__ x,
                                                     const float* __restrict__ gw) {
    int lane = threadIdx.x & 31;
    int t = blockIdx.x * 4 + (threadIdx.x >> 5);
    if (t >= Td) return;
    float xr[64];
    const float* xp = x + (size_t)t * Hd;
    #pragma unroll
    for (int j = 0; j < 64; j++) xr[j] = xp[lane + 32 * j];
    __half* xh = g_xh + (size_t)t * Hd;
    #pragma unroll
    for (int j = 0; j < 64; j++) xh[lane + 32 * j] = __float2half_rn(xr[j]);
    float logit[16];
    #pragma unroll
    for (int e = 0; e < 16; e++) {
        const float* g = gw + e * Hd;
        float s = 0.f;
        #pragma unroll
        for (int j = 0; j < 64; j++) s = fmaf(xr[j], g[lane + 32 * j], s);
        #pragma unroll
        for (int o = 16; o > 0; o >>= 1) s += __shfl_xor_sync(0xffffffffu, s, o);
        logit[e] = s;
    }
    if (lane == 0) {
        float mx = logit[0];
        #pragma unroll
        for (int e = 1; e < 16; e++) mx = fmaxf(mx, logit[e]);
        float p[16]; float den = 0.f;
        #pragma unroll
        for (int e = 0; e < 16; e++) { p[e] = expf(logit[e] - mx); den += p[e]; }
        int i1 = 0; float v1 = p[0];
        #pragma unroll
        for (int e = 1; e < 16; e++) if (p[e] > v1) { v1 = p[e]; i1 = e; }
        int i2 = -1; float v2 = -1.f;
        #pragma unroll
        for (int e = 0; e < 16; e++) if (e != i1 && p[e] > v2) { v2 = p[e]; i2 = e; }
        float inv = 1.f / den;
        g_topk_idx[2 * t]     = i1;
        g_topk_idx[2 * t + 1] = i2;
        g_topk_w[2 * t]       = v1 * inv;
        g_topk_w[2 * t + 1]   = v2 * inv;
        atomicAdd(&g_counts[i1], 1);
        atomicAdd(&g_counts[i2], 1);
    }
}

// ---------------- gate+up GEMM + overlapped phase-2 conversion --------------
// GEMM tile: 128(M) x 64(N per matrix) x 64(K). 256 threads, warps 4(M)x2(N).
// Stage (halves): A[128][72] (9216), Bg[64][72] (4608), Bu[64][72] (4608).
// 3 stages = 110592 B (2 CTAs/SM). Row stride 144 B -> conflict-free LDSM.
//
// Heterogeneous grid: 3520 GEMM blocks + 4096 cvt blocks, bid-interleaved so
// SMs co-host one tensor-bound GEMM CTA and one DRAM-bound cvt CTA.
// cvt blocks convert wd/wsd to fp16 and zero `out` — all only needed by the
// down kernel, which launches after this kernel completes (stream order).
#define GU_GEMM_BLOCKS 3520
#define GU_SHARED_BLOCKS 704
#define CVT2_BLOCKS 4096
#define GU_TOTAL_BLOCKS (GU_GEMM_BLOCKS + CVT2_BLOCKS)   // 7616
#define GU_IL (2 * GU_GEMM_BLOCKS)                       // 7040 interleave zone

// phase-2 segments in float4 units: wd, wsd, out-zero
#define P2_0 (S_WGE)                    // wd     = 11534336
#define P2_1 (P2_0 + S_WS)              // +wsd   = 12976128
#define P2_2 (P2_1 + 1048576u)          // +out   = 14024704

__global__ void __launch_bounds__(256) gateup_all_kernel(
    const float4* __restrict__ wd, const float4* __restrict__ wsd,
    float4* __restrict__ out) {
    extern __shared__ __half sm[];
    __shared__ int tok_s[128];
    const int tid = threadIdx.x;
    const int bid = blockIdx.x;

    // ---- decode heterogeneous grid ----
    int gemm_id, cvt_id;
    if (bid < GU_IL) {
        if (bid & 1) { cvt_id = bid >> 1; gemm_id = -1; }
        else         { gemm_id = bid >> 1; cvt_id = -1; }
    } else {
        cvt_id = GU_GEMM_BLOCKS + (bid - GU_IL); gemm_id = -1;
    }

    if (gemm_id < 0) {
        // ---- phase-2 conversion path (no smem, no syncs) ----
        for (uint32_t i = cvt_id * 256 + tid; i < P2_2; i += CVT2_BLOCKS * 256) {
            if (i < P2_0)      cvt_store((uint2*)g_wd_h,  wd,  i);
            else if (i < P2_1) cvt_store((uint2*)g_wsd_h, wsd, i - P2_0);
            else               out[i - P2_1] = make_float4(0.f, 0.f, 0.f, 0.f);
        }
        return;
    }

    // ---- GEMM path ----
    const int lane = tid & 31, wid = tid >> 5;
    const int wm = wid & 3, wn = wid >> 2;
    bool routed; int e, n0, r0, N;
    if (gemm_id < GU_SHARED_BLOCKS) {
        routed = false; N = ISd; e = 0;
        n0 = (gemm_id % 44) * 64; r0 = (gemm_id / 44) * 128;
    } else {
        int b = gemm_id - GU_SHARED_BLOCKS;
        routed = true; N = Id;
        n0 = (b % 22) * 64; int t = b / 22;
        r0 = (t & 7) * 128; e = t >> 3;
    }

    int C, base;
    if (routed) { C = g_counts[e]; base = g_offs[e]; }
    else        { C = Td;          base = 0; }
    if (r0 >= C) return;

    const __half* WgE = routed ? g_wg_h + (size_t)e * Hd * N : g_wsg_h;
    const __half* WuE = routed ? g_wu_h + (size_t)e * Hd * N : g_wsu_h;
    __half* ACT = routed ? g_act : g_sact;

    if (tid < 128) {
        int r = r0 + tid;
        tok_s[tid] = (r < C) ? (routed ? g_slot_token[base + r] : r) : -1;
    }
    __syncthreads();

    auto issue = [&](int st, int kt) {
        __half* As = sm + st * 18432;
        __half* Bg = As + 9216;
        __half* Bu = Bg + 4608;
        int k0 = kt * 64;
        #pragma unroll
        for (int i = 0; i < 4; i++) {       // A: 128 rows x 8 chunks
            int idx = tid + i * 256;
            int row = idx >> 3, kc = (idx & 7) * 8;
            int tok = tok_s[row];
            const __half* src = g_xh + (size_t)(tok < 0 ? 0 : tok) * Hd + k0 + kc;
            cp16h(&As[row * 72 + kc], src, tok >= 0);
        }
        #pragma unroll
        for (int i = 0; i < 2; i++) {       // B: 64 rows x 8 chunks each matrix
            int idx = tid + i * 256;
            int row = idx >> 3, nc = (idx & 7) * 8;
            size_t go = (size_t)(k0 + row) * N + n0 + nc;
            cp16h(&Bg[row * 72 + nc], WgE + go, true);
            cp16h(&Bu[row * 72 + nc], WuE + go, true);
        }
        CP_COMMIT();
    };

    float accg[2][4][4] = {};
    float accu[2][4][4] = {};

    auto compute = [&](int st) {
        const __half* As = sm + st * 18432;
        const __half* Bg = As + 9216;
        const __half* Bu = Bg + 4608;
        #pragma unroll
        for (int kk = 0; kk < 4; kk++) {
            uint32_t a[2][4];
            #pragma unroll
            for (int mt = 0; mt < 2; mt++) {
                uint32_t ad = s2u(&As[(wm * 32 + mt * 16 + (lane & 15)) * 72 +
                                      kk * 16 + (lane >> 4) * 8]);
                ldsm4(a[mt], ad);
            }
            #pragma unroll
            for (int np = 0; np < 2; np++) {
                uint32_t bg[4], bu[4];
                int rowk = kk * 16 + (lane & 15);
                int ncol = wn * 32 + np * 16 + (lane >> 4) * 8;
                ldsm4t(bg, s2u(&Bg[rowk * 72 + ncol]));
                ldsm4t(bu, s2u(&Bu[rowk * 72 + ncol]));
                #pragma unroll
                for (int j = 0; j < 2; j++) {
                    int nt = np * 2 + j;
                    #pragma unroll
                    for (int mt = 0; mt < 2; mt++) {
                        mma16(accg[mt][nt], a[mt], bg[2 * j], bg[2 * j + 1]);
                        mma16(accu[mt][nt], a[mt], bu[2 * j], bu[2 * j + 1]);
                    }
                }
            }
        }
    };

    const int NK = Hd / 64;  // 32
    issue(0, 0);
    issue(1, 1);
    for (int kt = 0; kt < NK; kt++) {
        if (kt < NK - 1) asm volatile("cp.async.wait_group 1;\n");
        else             asm volatile("cp.async.wait_group 0;\n");
        __syncthreads();
        if (kt + 2 < NK) issue((kt + 2) % 3, kt + 2);
        compute(kt % 3);
    }

    #pragma unroll
    for (int mt = 0; mt < 2; mt++)
    #pragma unroll
    for (int nt = 0; nt < 4; nt++)
    #pragma unroll
    for (int ih = 0; ih < 2; ih++) {
        int rl = wm * 32 + mt * 16 + (lane >> 2) + ih * 8;
        int r = r0 + rl;
        if (r < C) {
            int col = n0 + wn * 32 + nt * 8 + 2 * (lane & 3);
            float g0 = accg[mt][nt][2 * ih], u0 = accu[mt][nt][2 * ih];
            float g1 = accg[mt][nt][2 * ih + 1], u1 = accu[mt][nt][2 * ih + 1];
            float a0 = g0 / (1.f + __expf(-g0)) * u0;
            float a1 = g1 / (1.f + __expf(-g1)) * u1;
            *(__half2*)&ACT[(size_t)(base + r) * N + col] = __floats2half2_rn(a0, a1);
        }
    }
}

// ---------------- merged down-proj GEMM (shared + routed in one launch) -----
// Tile: 128(M) x 128(N) x 64(K). 256 threads, warps 4(M) x 2(N), warp = 32x64.
// Stage (halves): A[128][72] (9216), B[64][136] (8704). 3 st = 107520 B.
// out is pre-zeroed (by gateup's cvt blocks); EVERY epilogue write is
// atomicAdd (shared rows weight 1.0), so block execution order is irrelevant.
#define DN_SHARED_BLOCKS 256
#define DN_TOTAL_BLOCKS  2304
__global__ void __launch_bounds__(256) down_all_kernel(float* __restrict__ out) {
    extern __shared__ __half sm[];
    __shared__ int tok_s[128];
    __shared__ float w_s[128];
    const int tid = threadIdx.x;
    const int lane = tid & 31, wid = tid >> 5;
    const int wm = wid & 3, wn = wid >> 2;
    const int bid = blockIdx.x;

    bool routed; int e, n0, r0, K;
    if (bid < DN_SHARED_BLOCKS) {
        routed = false; K = ISd; e = 0;
        n0 = (bid & 15) * 128; r0 = (bid >> 4) * 128;
    } else {
        int b = bid - DN_SHARED_BLOCKS;
        routed = true; K = Id;
        n0 = (b & 15) * 128; int t = b >> 4;
        r0 = (t & 7) * 128; e = t >> 3;
    }

    int C, base;
    if (routed) { C = g_counts[e]; base = g_offs[e]; }
    else        { C = Td;          base = 0; }
    if (r0 >= C) return;

    const __half* A   = routed ? g_act : g_sact;
    const __half* WdE = routed ? g_wd_h + (size_t)e * K * Hd : g_wsd_h;

    if (tid < 128) {
        int r = r0 + tid;
        bool v = (r < C);
        tok_s[tid] = v ? (routed ? g_slot_token[base + r] : r) : -1;
        w_s[tid]   = v ? (routed ? g_slot_w[base + r] : 1.0f) : 0.f;
    }
    __syncthreads();

    auto issue = [&](int st, int kt) {
        __half* As = sm + st * 17920;
        __half* Bs = As + 9216;
        int k0 = kt * 64;
        #pragma unroll
        for (int i = 0; i < 4; i++) {       // A: 128 rows x 8 chunks
            int idx = tid + i * 256;
            int row = idx >> 3, kc = (idx & 7) * 8;
            bool pred = (r0 + row) < C;
            const __half* src = A + (size_t)(base + (pred ? (r0 + row) : 0)) * K + k0 + kc;
            cp16h(&As[row * 72 + kc], src, pred);
        }
        #pragma unroll
        for (int i = 0; i < 4; i++) {       // B: 64 rows x 16 chunks
            int idx = tid + i * 256;
            int row = idx >> 4, nc = (idx & 15) * 8;
            cp16h(&Bs[row * 136 + nc], WdE + (size_t)(k0 + row) * Hd + n0 + nc, true);
        }
        CP_COMMIT();
    };

    float acc[2][8][4] = {};

    auto compute = [&](int st) {
        const __half* As = sm + st * 17920;
        const __half* Bs = As + 9216;
        #pragma unroll
        for (int kk = 0; kk < 4; kk++) {
            uint32_t a[2][4];
            #pragma unroll
            for (int mt = 0; mt < 2; mt++) {
                uint32_t ad = s2u(&As[(wm * 32 + mt * 16 + (lane & 15)) * 72 +
                                      kk * 16 + (lane >> 4) * 8]);
                ldsm4(a[mt], ad);
            }
            #pragma unroll
            for (int np = 0; np < 4; np++) {
                uint32_t b[4];
                int rowk = kk * 16 + (lane & 15);
                int ncol = wn * 64 + np * 16 + (lane >> 4) * 8;
                ldsm4t(b, s2u(&Bs[rowk * 136 + ncol]));
                #pragma unroll
                for (int j = 0; j < 2; j++) {
                    int nt = np * 2 + j;
                    #pragma unroll
                    for (int mt = 0; mt < 2; mt++)
                        mma16(acc[mt][nt], a[mt], b[2 * j], b[2 * j + 1]);
                }
            }
        }
    };

    const int NK = K / 64;  // 44 (shared) or 22 (routed)
    issue(0, 0);
    issue(1, 1);
    for (int kt = 0; kt < NK; kt++) {
        if (kt < NK - 1) asm volatile("cp.async.wait_group 1;\n");
        else             asm volatile("cp.async.wait_group 0;\n");
        __syncthreads();
        if (kt + 2 < NK) issue((kt + 2) % 3, kt + 2);
        compute(kt % 3);
    }

    #pragma unroll
    for (int mt = 0; mt < 2; mt++)
    #pragma unroll
    for (int nt = 0; nt < 8; nt++)
    #pragma unroll
    for (int i = 0; i < 4; i++) {
        int rl = wm * 32 + mt * 16 + (lane >> 2) + (i >> 1) * 8;
        int col = n0 + wn * 64 + nt * 8 + 2 * (lane & 3) + (i & 1);
        if (r0 + rl < C) {
            int t = tok_s[rl];
            atomicAdd(out + (size_t)t * Hd + col, w_s[rl] * acc[mt][nt][i]);
        }
    }
}

// ---------------- launcher ----------------
extern "C" void kernel_launch(void* const* d_in, const int* in_sizes, int n_in,
                              void* d_out, int out_size) {
    (void)in_sizes; (void)n_in; (void)out_size;
    const float* x   = (const float*)d_in[0];
    const float* gw  = (const float*)d_in[1];
    const float* wg  = (const float*)d_in[2];
    const float* wu  = (const float*)d_in[3];
    const float* wd  = (const float*)d_in[4];
    const float* wsg = (const float*)d_in[5];
    const float* wsu = (const float*)d_in[6];
    const float* wsd = (const float*)d_in[7];
    float* out = (float*)d_out;

    const int GU_SMEM = 3 * 18432 * 2;   // 110592
    const int DN_SMEM = 3 * 17920 * 2;   // 107520
    cudaFuncSetAttribute(gateup_all_kernel, cudaFuncAttributeMaxDynamicSharedMemorySize, GU_SMEM);
    cudaFuncSetAttribute(down_all_kernel,   cudaFuncAttributeMaxDynamicSharedMemorySize, DN_SMEM);

    zero_kernel<<<1, 32>>>();
    router_kernel<<<512, 128>>>(x, gw);       // also writes g_xh (fp16 x)
    dispatch_kernel<<<1, 1024>>>();

    // phase-1 cvt: only what gate/up needs (wg, wu, wsg, wsu)
    cvt1_kernel<<<8192, 256>>>((const float4*)wg,  (const float4*)wu,
                               (const float4*)wsg, (const float4*)wsu);

    // gate/up GEMM (3520 blocks) + overlapped phase-2 cvt (4096 blocks:
    // wd, wsd, out-zero), bid-interleaved
    gateup_all_kernel<<<GU_TOTAL_BLOCKS, 256, GU_SMEM>>>(
        (const float4*)wd, (const float4*)wsd, (float4*)out);

    // merged down: atomicAdd onto the pre-zeroed out
    down_all_kernel<<<DN_TOTAL_BLOCKS, 256, DN_SMEM>>>(out);
}

// round 15
// speedup vs baseline: 1.5152x; 1.0622x over previous
#include <cuda_runtime.h>
#include <cuda_fp16.h>
#include <cstdint>
#include <math.h>

// Problem dims
#define Hd 2048
#define Ed 16
#define Td 2048
#define Id 1408
#define ISd 2816

// ---------------- scratch (static device globals; no allocs) ----------------
__device__ __half g_xh[2048 * 2048];           // x in fp16 (written by router)
__device__ __half g_wg_h[16 * 2048 * 1408];    // routed gate weights fp16
__device__ __half g_wu_h[16 * 2048 * 1408];    // routed up weights fp16
__device__ __half g_wd_h[16 * 1408 * 2048];    // routed down weights fp16
__device__ __half g_wsg_h[2048 * 2816];        // shared gate fp16
__device__ __half g_wsu_h[2048 * 2816];        // shared up fp16
__device__ __half g_wsd_h[2816 * 2048];        // shared down fp16
__device__ __half g_act[4096 * 1408];          // compact routed activations fp16
__device__ __half g_sact[2048 * 2816];         // shared-expert activations fp16
__device__ int   g_slot_token[4096];
__device__ float g_slot_w[4096];
__device__ int   g_topk_idx[2048 * 2];
__device__ float g_topk_w[2048 * 2];
__device__ int   g_counts[16];
__device__ int   g_offs[16];

// ---------------- helpers ----------------
__device__ __forceinline__ void mma16(float* c, const uint32_t* a, uint32_t b0, uint32_t b1) {
    asm volatile(
        "mma.sync.aligned.m16n8k16.row.col.f32.f16.f16.f32 "
        "{%0,%1,%2,%3}, {%4,%5,%6,%7}, {%8,%9}, {%0,%1,%2,%3};\n"
        : "+f"(c[0]), "+f"(c[1]), "+f"(c[2]), "+f"(c[3])
        : "r"(a[0]), "r"(a[1]), "r"(a[2]), "r"(a[3]), "r"(b0), "r"(b1));
}

__device__ __forceinline__ void cp16h(__half* s, const __half* g, bool pred) {
    uint32_t sa = (uint32_t)__cvta_generic_to_shared(s);
    int sz = pred ? 16 : 0;
    asm volatile("cp.async.cg.shared.global [%0], [%1], 16, %2;\n"
                 :: "r"(sa), "l"(g), "r"(sz));
}
#define CP_COMMIT() asm volatile("cp.async.commit_group;\n")

__device__ __forceinline__ uint32_t s2u(const void* p) {
    return (uint32_t)__cvta_generic_to_shared(p);
}

__device__ __forceinline__ void ldsm4(uint32_t* r, uint32_t a) {
    asm volatile("ldmatrix.sync.aligned.m8n8.x4.shared.b16 {%0,%1,%2,%3}, [%4];"
                 : "=r"(r[0]), "=r"(r[1]), "=r"(r[2]), "=r"(r[3]) : "r"(a));
}
__device__ __forceinline__ void ldsm4t(uint32_t* r, uint32_t a) {
    asm volatile("ldmatrix.sync.aligned.m8n8.x4.trans.shared.b16 {%0,%1,%2,%3}, [%4];"
                 : "=r"(r[0]), "=r"(r[1]), "=r"(r[2]), "=r"(r[3]) : "r"(a));
}

__device__ __forceinline__ void cvt_store(uint2* dst, const float4* src, uint32_t off) {
    float4 v = src[off];
    __half2 h0 = __floats2half2_rn(v.x, v.y);
    __half2 h1 = __floats2half2_rn(v.z, v.w);
    dst[off] = make_uint2(*(uint32_t*)&h0, *(uint32_t*)&h1);
}

// ---------------- phase-1 conversion (weights needed by gate/up) ------------
// Segments in float4 units: wg, wu, wsg, wsu.
#define S_WGE  11534336u                // 16*2048*1408/4
#define S_WS   1441792u                 // 2048*2816/4
#define P1_0 (S_WGE)
#define P1_1 (P1_0 + S_WGE)
#define P1_2 (P1_1 + S_WS)
#define P1_3 (P1_2 + S_WS)             // total = 25952256

__global__ void __launch_bounds__(256) cvt1_kernel(
    const float4* __restrict__ wg,  const float4* __restrict__ wu,
    const float4* __restrict__ wsg, const float4* __restrict__ wsu) {
    for (uint32_t i = blockIdx.x * blockDim.x + threadIdx.x; i < P1_3;
         i += gridDim.x * blockDim.x) {
        if (i < P1_0)      cvt_store((uint2*)g_wg_h,  wg,  i);
        else if (i < P1_1) cvt_store((uint2*)g_wu_h,  wu,  i - P1_0);
        else if (i < P1_2) cvt_store((uint2*)g_wsg_h, wsg, i - P1_1);
        else               cvt_store((uint2*)g_wsu_h, wsu, i - P1_2);
    }
}

// ---------------- tiny kernels ----------------
__global__ void zero_kernel() {
    if (threadIdx.x < 16) g_counts[threadIdx.x] = 0;
}

// Single block: prefix scan over counts + compact slot-list build.
__global__ void __launch_bounds__(1024) dispatch_kernel() {
    __shared__ int soffs[16];
    __shared__ int scur[16];
    int tid = threadIdx.x;
    if (tid == 0) {
        int off = 0;
        #pragma unroll
        for (int e = 0; e < 16; e++) {
            soffs[e] = off; g_offs[e] = off; off += g_counts[e];
        }
    }
    if (tid < 16) scur[tid] = 0;
    __syncthreads();
    for (int t = tid; t < Td; t += 1024) {
        #pragma unroll
        for (int k = 0; k < 2; k++) {
            int e = g_topk_idx[2 * t + k];
            int p = atomicAdd(&scur[e], 1);
            int s = soffs[e] + p;
            g_slot_token[s] = t;
            g_slot_w[s] = g_topk_w[2 * t + k];
        }
    }
}

// One warp per token: logits -> softmax -> top-2 -> histogram.
// Also emits the fp16 copy of x (row already resident in registers).
__global__ void __launch_bounds__(128) router_kernel(const float* __restrict__ x,
                                                     const float* __restrict__ gw) {
    int lane = threadIdx.x & 31;
    int t = blockIdx.x * 4 + (threadIdx.x >> 5);
    if (t >= Td) return;
    float xr[64];
    const float* xp = x + (size_t)t * Hd;
    #pragma unroll
    for (int j = 0; j < 64; j++) xr[j] = xp[lane + 32 * j];
    __half* xh = g_xh + (size_t)t * Hd;
    #pragma unroll
    for (int j = 0; j < 64; j++) xh[lane + 32 * j] = __float2half_rn(xr[j]);
    float logit[16];
    #pragma unroll
    for (int e = 0; e < 16; e++) {
        const float* g = gw + e * Hd;
        float s = 0.f;
        #pragma unroll
        for (int j = 0; j < 64; j++) s = fmaf(xr[j], g[lane + 32 * j], s);
        #pragma unroll
        for (int o = 16; o > 0; o >>= 1) s += __shfl_xor_sync(0xffffffffu, s, o);
        logit[e] = s;
    }
    if (lane == 0) {
        float mx = logit[0];
        #pragma unroll
        for (int e = 1; e < 16; e++) mx = fmaxf(mx, logit[e]);
        float p[16]; float den = 0.f;
        #pragma unroll
        for (int e = 0; e < 16; e++) { p[e] = expf(logit[e] - mx); den += p[e]; }
        int i1 = 0; float v1 = p[0];
        #pragma unroll
        for (int e = 1; e < 16; e++) if (p[e] > v1) { v1 = p[e]; i1 = e; }
        int i2 = -1; float v2 = -1.f;
        #pragma unroll
        for (int e = 0; e < 16; e++) if (e != i1 && p[e] > v2) { v2 = p[e]; i2 = e; }
        float inv = 1.f / den;
        g_topk_idx[2 * t]     = i1;
        g_topk_idx[2 * t + 1] = i2;
        g_topk_w[2 * t]       = v1 * inv;
        g_topk_w[2 * t + 1]   = v2 * inv;
        atomicAdd(&g_counts[i1], 1);
        atomicAdd(&g_counts[i2], 1);
    }
}

// ---------------- gate+up GEMM + overlapped phase-2 conversion --------------
// GEMM tile: 128(M) x 64(N per matrix) x 64(K). 256 threads, warps 4(M)x2(N).
// Stage (halves): A[128][72] (9216), Bg[64][72] (4608), Bu[64][72] (4608).
// 3 stages = 110592 B (2 CTAs/SM). Row stride 144 B -> conflict-free LDSM.
//
// Heterogeneous grid: 3520 GEMM blocks + 4096 cvt blocks, bid-interleaved so
// SMs co-host one tensor-bound GEMM CTA and one DRAM-bound cvt CTA.
// cvt blocks convert wd/wsd to fp16 and zero `out` — all only needed by the
// down kernel, which launches after this kernel completes (stream order).
//
// R14 finding: the cvt path was MLP=1 (dependent load->store), capping mixed-
// kernel DRAM at ~1.4 TB/s and making cvt2 the binding tail of this launch.
// Fix: batch 4 independent loads per thread per iteration (16 KB in flight
// per SM at 1 cvt CTA/SM -> ~4-5 TB/s).
#define GU_GEMM_BLOCKS 3520
#define GU_SHARED_BLOCKS 704
#define CVT2_BLOCKS 4096
#define GU_TOTAL_BLOCKS (GU_GEMM_BLOCKS + CVT2_BLOCKS)   // 7616
#define GU_IL (2 * GU_GEMM_BLOCKS)                       // 7040 interleave zone

// phase-2 segments in float4 units: wd, wsd, out-zero
#define P2_0 (S_WGE)                    // wd     = 11534336
#define P2_1 (P2_0 + S_WS)              // +wsd   = 12976128
#define P2_2 (P2_1 + 1048576u)          // +out   = 14024704

__global__ void __launch_bounds__(256) gateup_all_kernel(
    const float4* __restrict__ wd, const float4* __restrict__ wsd,
    float4* __restrict__ out) {
    extern __shared__ __half sm[];
    __shared__ int tok_s[128];
    const int tid = threadIdx.x;
    const int bid = blockIdx.x;

    // ---- decode heterogeneous grid ----
    int gemm_id, cvt_id;
    if (bid < GU_IL) {
        if (bid & 1) { cvt_id = bid >> 1; gemm_id = -1; }
        else         { gemm_id = bid >> 1; cvt_id = -1; }
    } else {
        cvt_id = GU_GEMM_BLOCKS + (bid - GU_IL); gemm_id = -1;
    }

    if (gemm_id < 0) {
        // ---- phase-2 conversion path: 4 independent loads per iteration ----
        for (uint32_t base = cvt_id * 1024u; base < P2_2;
             base += CVT2_BLOCKS * 1024u) {
            float4 v[4]; uint32_t ix[4]; bool ok[4];
            #pragma unroll
            for (int j = 0; j < 4; j++) {
                uint32_t i = base + tid + j * 256u;
                ix[j] = i; ok[j] = (i < P2_2);
                if (ok[j]) {
                    if (i < P2_0)      v[j] = wd[i];
                    else if (i < P2_1) v[j] = wsd[i - P2_0];
                    else               v[j] = make_float4(0.f, 0.f, 0.f, 0.f);
                }
            }
            #pragma unroll
            for (int j = 0; j < 4; j++) {
                if (!ok[j]) continue;
                uint32_t i = ix[j];
                if (i >= P2_1) { out[i - P2_1] = v[j]; continue; }
                __half2 h0 = __floats2half2_rn(v[j].x, v[j].y);
                __half2 h1 = __floats2half2_rn(v[j].z, v[j].w);
                uint2 pk = make_uint2(*(uint32_t*)&h0, *(uint32_t*)&h1);
                if (i < P2_0) ((uint2*)g_wd_h)[i] = pk;
                else          ((uint2*)g_wsd_h)[i - P2_0] = pk;
            }
        }
        return;
    }

    // ---- GEMM path ----
    const int lane = tid & 31, wid = tid >> 5;
    const int wm = wid & 3, wn = wid >> 2;
    bool routed; int e, n0, r0, N;
    if (gemm_id < GU_SHARED_BLOCKS) {
        routed = false; N = ISd; e = 0;
        n0 = (gemm_id % 44) * 64; r0 = (gemm_id / 44) * 128;
    } else {
        int b = gemm_id - GU_SHARED_BLOCKS;
        routed = true; N = Id;
        n0 = (b % 22) * 64; int t = b / 22;
        r0 = (t & 7) * 128; e = t >> 3;
    }

    int C, base;
    if (routed) { C = g_counts[e]; base = g_offs[e]; }
    else        { C = Td;          base = 0; }
    if (r0 >= C) return;

    const __half* WgE = routed ? g_wg_h + (size_t)e * Hd * N : g_wsg_h;
    const __half* WuE = routed ? g_wu_h + (size_t)e * Hd * N : g_wsu_h;
    __half* ACT = routed ? g_act : g_sact;

    if (tid < 128) {
        int r = r0 + tid;
        tok_s[tid] = (r < C) ? (routed ? g_slot_token[base + r] : r) : -1;
    }
    __syncthreads();

    auto issue = [&](int st, int kt) {
        __half* As = sm + st * 18432;
        __half* Bg = As + 9216;
        __half* Bu = Bg + 4608;
        int k0 = kt * 64;
        #pragma unroll
        for (int i = 0; i < 4; i++) {       // A: 128 rows x 8 chunks
            int idx = tid + i * 256;
            int row = idx >> 3, kc = (idx & 7) * 8;
            int tok = tok_s[row];
            const __half* src = g_xh + (size_t)(tok < 0 ? 0 : tok) * Hd + k0 + kc;
            cp16h(&As[row * 72 + kc], src, tok >= 0);
        }
        #pragma unroll
        for (int i = 0; i < 2; i++) {       // B: 64 rows x 8 chunks each matrix
            int idx = tid + i * 256;
            int row = idx >> 3, nc = (idx & 7) * 8;
            size_t go = (size_t)(k0 + row) * N + n0 + nc;
            cp16h(&Bg[row * 72 + nc], WgE + go, true);
            cp16h(&Bu[row * 72 + nc], WuE + go, true);
        }
        CP_COMMIT();
    };

    float accg[2][4][4] = {};
    float accu[2][4][4] = {};

    auto compute = [&](int st) {
        const __half* As = sm + st * 18432;
        const __half* Bg = As + 9216;
        const __half* Bu = Bg + 4608;
        #pragma unroll
        for (int kk = 0; kk < 4; kk++) {
            uint32_t a[2][4];
            #pragma unroll
            for (int mt = 0; mt < 2; mt++) {
                uint32_t ad = s2u(&As[(wm * 32 + mt * 16 + (lane & 15)) * 72 +
                                      kk * 16 + (lane >> 4) * 8]);
                ldsm4(a[mt], ad);
            }
            #pragma unroll
            for (int np = 0; np < 2; np++) {
                uint32_t bg[4], bu[4];
                int rowk = kk * 16 + (lane & 15);
                int ncol = wn * 32 + np * 16 + (lane >> 4) * 8;
                ldsm4t(bg, s2u(&Bg[rowk * 72 + ncol]));
                ldsm4t(bu, s2u(&Bu[rowk * 72 + ncol]));
                #pragma unroll
                for (int j = 0; j < 2; j++) {
                    int nt = np * 2 + j;
                    #pragma unroll
                    for (int mt = 0; mt < 2; mt++) {
                        mma16(accg[mt][nt], a[mt], bg[2 * j], bg[2 * j + 1]);
                        mma16(accu[mt][nt], a[mt], bu[2 * j], bu[2 * j + 1]);
                    }
                }
            }
        }
    };

    const int NK = Hd / 64;  // 32
    issue(0, 0);
    issue(1, 1);
    for (int kt = 0; kt < NK; kt++) {
        if (kt < NK - 1) asm volatile("cp.async.wait_group 1;\n");
        else             asm volatile("cp.async.wait_group 0;\n");
        __syncthreads();
        if (kt + 2 < NK) issue((kt + 2) % 3, kt + 2);
        compute(kt % 3);
    }

    #pragma unroll
    for (int mt = 0; mt < 2; mt++)
    #pragma unroll
    for (int nt = 0; nt < 4; nt++)
    #pragma unroll
    for (int ih = 0; ih < 2; ih++) {
        int rl = wm * 32 + mt * 16 + (lane >> 2) + ih * 8;
        int r = r0 + rl;
        if (r < C) {
            int col = n0 + wn * 32 + nt * 8 + 2 * (lane & 3);
            float g0 = accg[mt][nt][2 * ih], u0 = accu[mt][nt][2 * ih];
            float g1 = accg[mt][nt][2 * ih + 1], u1 = accu[mt][nt][2 * ih + 1];
            float a0 = g0 / (1.f + __expf(-g0)) * u0;
            float a1 = g1 / (1.f + __expf(-g1)) * u1;
            *(__half2*)&ACT[(size_t)(base + r) * N + col] = __floats2half2_rn(a0, a1);
        }
    }
}

// ---------------- merged down-proj GEMM (shared + routed in one launch) -----
// Tile: 128(M) x 128(N) x 64(K). 256 threads, warps 4(M) x 2(N), warp = 32x64.
// Stage (halves): A[128][72] (9216), B[64][136] (8704). 3 st = 107520 B.
// out is pre-zeroed (by gateup's cvt blocks); EVERY epilogue write is
// atomicAdd (shared rows weight 1.0), so block execution order is irrelevant.
#define DN_SHARED_BLOCKS 256
#define DN_TOTAL_BLOCKS  2304
__global__ void __launch_bounds__(256) down_all_kernel(float* __restrict__ out) {
    extern __shared__ __half sm[];
    __shared__ int tok_s[128];
    __shared__ float w_s[128];
    const int tid = threadIdx.x;
    const int lane = tid & 31, wid = tid >> 5;
    const int wm = wid & 3, wn = wid >> 2;
    const int bid = blockIdx.x;

    bool routed; int e, n0, r0, K;
    if (bid < DN_SHARED_BLOCKS) {
        routed = false; K = ISd; e = 0;
        n0 = (bid & 15) * 128; r0 = (bid >> 4) * 128;
    } else {
        int b = bid - DN_SHARED_BLOCKS;
        routed = true; K = Id;
        n0 = (b & 15) * 128; int t = b >> 4;
        r0 = (t & 7) * 128; e = t >> 3;
    }

    int C, base;
    if (routed) { C = g_counts[e]; base = g_offs[e]; }
    else        { C = Td;          base = 0; }
    if (r0 >= C) return;

    const __half* A   = routed ? g_act : g_sact;
    const __half* WdE = routed ? g_wd_h + (size_t)e * K * Hd : g_wsd_h;

    if (tid < 128) {
        int r = r0 + tid;
        bool v = (r < C);
        tok_s[tid] = v ? (routed ? g_slot_token[base + r] : r) : -1;
        w_s[tid]   = v ? (routed ? g_slot_w[base + r] : 1.0f) : 0.f;
    }
    __syncthreads();

    auto issue = [&](int st, int kt) {
        __half* As = sm + st * 17920;
        __half* Bs = As + 9216;
        int k0 = kt * 64;
        #pragma unroll
        for (int i = 0; i < 4; i++) {       // A: 128 rows x 8 chunks
            int idx = tid + i * 256;
            int row = idx >> 3, kc = (idx & 7) * 8;
            bool pred = (r0 + row) < C;
            const __half* src = A + (size_t)(base + (pred ? (r0 + row) : 0)) * K + k0 + kc;
            cp16h(&As[row * 72 + kc], src, pred);
        }
        #pragma unroll
        for (int i = 0; i < 4; i++) {       // B: 64 rows x 16 chunks
            int idx = tid + i * 256;
            int row = idx >> 4, nc = (idx & 15) * 8;
            cp16h(&Bs[row * 136 + nc], WdE + (size_t)(k0 + row) * Hd + n0 + nc, true);
        }
        CP_COMMIT();
    };

    float acc[2][8][4] = {};

    auto compute = [&](int st) {
        const __half* As = sm + st * 17920;
        const __half* Bs = As + 9216;
        #pragma unroll
        for (int kk = 0; kk < 4; kk++) {
            uint32_t a[2][4];
            #pragma unroll
            for (int mt = 0; mt < 2; mt++) {
                uint32_t ad = s2u(&As[(wm * 32 + mt * 16 + (lane & 15)) * 72 +
                                      kk * 16 + (lane >> 4) * 8]);
                ldsm4(a[mt], ad);
            }
            #pragma unroll
            for (int np = 0; np < 4; np++) {
                uint32_t b[4];
                int rowk = kk * 16 + (lane & 15);
                int ncol = wn * 64 + np * 16 + (lane >> 4) * 8;
                ldsm4t(b, s2u(&Bs[rowk * 136 + ncol]));
                #pragma unroll
                for (int j = 0; j < 2; j++) {
                    int nt = np * 2 + j;
                    #pragma unroll
                    for (int mt = 0; mt < 2; mt++)
                        mma16(acc[mt][nt], a[mt], b[2 * j], b[2 * j + 1]);
                }
            }
        }
    };

    const int NK = K / 64;  // 44 (shared) or 22 (routed)
    issue(0, 0);
    issue(1, 1);
    for (int kt = 0; kt < NK; kt++) {
        if (kt < NK - 1) asm volatile("cp.async.wait_group 1;\n");
        else             asm volatile("cp.async.wait_group 0;\n");
        __syncthreads();
        if (kt + 2 < NK) issue((kt + 2) % 3, kt + 2);
        compute(kt % 3);
    }

    #pragma unroll
    for (int mt = 0; mt < 2; mt++)
    #pragma unroll
    for (int nt = 0; nt < 8; nt++)
    #pragma unroll
    for (int i = 0; i < 4; i++) {
        int rl = wm * 32 + mt * 16 + (lane >> 2) + (i >> 1) * 8;
        int col = n0 + wn * 64 + nt * 8 + 2 * (lane & 3) + (i & 1);
        if (r0 + rl < C) {
            int t = tok_s[rl];
            atomicAdd(out + (size_t)t * Hd + col, w_s[rl] * acc[mt][nt][i]);
        }
    }
}

// ---------------- launcher ----------------
extern "C" void kernel_launch(void* const* d_in, const int* in_sizes, int n_in,
                              void* d_out, int out_size) {
    (void)in_sizes; (void)n_in; (void)out_size;
    const float* x   = (const float*)d_in[0];
    const float* gw  = (const float*)d_in[1];
    const float* wg  = (const float*)d_in[2];
    const float* wu  = (const float*)d_in[3];
    const float* wd  = (const float*)d_in[4];
    const float* wsg = (const float*)d_in[5];
    const float* wsu = (const float*)d_in[6];
    const float* wsd = (const float*)d_in[7];
    float* out = (float*)d_out;

    const int GU_SMEM = 3 * 18432 * 2;   // 110592
    const int DN_SMEM = 3 * 17920 * 2;   // 107520
    cudaFuncSetAttribute(gateup_all_kernel, cudaFuncAttributeMaxDynamicSharedMemorySize, GU_SMEM);
    cudaFuncSetAttribute(down_all_kernel,   cudaFuncAttributeMaxDynamicSharedMemorySize, DN_SMEM);

    zero_kernel<<<1, 32>>>();
    router_kernel<<<512, 128>>>(x, gw);       // also writes g_xh (fp16 x)
    dispatch_kernel<<<1, 1024>>>();

    // phase-1 cvt: only what gate/up needs (wg, wu, wsg, wsu)
    cvt1_kernel<<<8192, 256>>>((const float4*)wg,  (const float4*)wu,
                               (const float4*)wsg, (const float4*)wsu);

    // gate/up GEMM (3520 blocks) + overlapped phase-2 cvt (4096 blocks:
    // wd, wsd, out-zero; 4-way batched loads), bid-interleaved
    gateup_all_kernel<<<GU_TOTAL_BLOCKS, 256, GU_SMEM>>>(
        (const float4*)wd, (const float4*)wsd, (float4*)out);

    // merged down: atomicAdd onto the pre-zeroed out
    down_all_kernel<<<DN_TOTAL_BLOCKS, 256, DN_SMEM>>>(out);
}